// round 14
// baseline (speedup 1.0000x reference)
#include <cuda_runtime.h>
#include <cstdint>

// Depthwise conv 31x31, pad 15, stride 1, fp32 — legacy tensor-core path.
// x: [32, 384, 56, 56], w: [384, 1, 31, 31], bias: [384], out same shape.
//
// mma.sync.m16n8k8 TF32 (sm_80+ PTX; runs on Blackwell tensor pipe via
// fallback HMMA — tcgen05 is blocked because the harness targets sm_103).
// Per CTA = one (n,c) plane. Per tap-row dy:
//     D[y][x] += sum_u InPad[y+dy][u] * W_dy[u][x],  W_dy[u][x] = w[dy][u-x]
// A = padded input rows (dy shift = row offset; staged once), B = weights,
// function of (u-x) only -> read from a 64-entry zero-padded weight line.
// Band-limited: j = ktile - ntile in [0,4] (j=5 proven all-zero, removed R12).
//
// R13: MMA loop nest swapped to j-outer / n-inner. The old n-outer order
// issued 5 consecutive MMAs RAW-dependent on the same acc[n] (serialized
// tensor chains -> issue 34%, tensor 72.7%). Now consecutive MMAs hit 7
// different accumulators (dep distance 7) and each j reuses one B fragment.

typedef unsigned int u32;

#define IPSTRIDE 100     // floats per InPad row; 100 mod 32 = 4 -> conflict-free
#define IPROWS   94      // rows 0..93 (y0+dy+g+8 max = 93), rows >=86 zero
#define NTH      128

static __device__ __forceinline__ u32 tf32r(float v) {
    u32 t;
    asm("cvt.rna.tf32.f32 %0, %1;" : "=r"(t) : "f"(v));
    return t;
}

#define MMA(acc, a, bb0, bb1)                                                  \
    asm("mma.sync.aligned.m16n8k8.row.col.f32.tf32.tf32.f32 "                  \
        "{%0,%1,%2,%3}, {%4,%5,%6,%7}, {%8,%9}, {%0,%1,%2,%3};"                \
        : "+f"((acc)[0]), "+f"((acc)[1]), "+f"((acc)[2]), "+f"((acc)[3])       \
        : "r"((a)[0]), "r"((a)[1]), "r"((a)[2]), "r"((a)[3]),                  \
          "r"(bb0), "r"(bb1))

__global__ void __launch_bounds__(NTH, 5)
dwconv31_tf32_hmma3_kernel(const float* __restrict__ x,
                           const float* __restrict__ w,
                           const float* __restrict__ bias,
                           float* __restrict__ out)
{
    extern __shared__ u32 sm[];
    u32* ip   = sm;                     // InPad: 94 x 100 tf32
    u32* wall = sm + IPROWS * IPSTRIDE; // 31 x 64 padded weight lines

    const int plane = blockIdx.x;          // n*384 + c
    const int c = plane - (plane / 384) * 384;
    const int tid = threadIdx.x;

    // Zero InPad (halo rows/cols), stage zero-padded weight lines.
#pragma unroll 1
    for (int i = tid; i < IPROWS * IPSTRIDE; i += NTH) ip[i] = 0u;
#pragma unroll 1
    for (int i = tid; i < 31 * 64; i += NTH) {
        int dy = i >> 6, p = i & 63, t = p - 8;
        float v = (t >= 0 && t < 31) ? w[c * 961 + dy * 31 + t] : 0.0f;
        wall[i] = tf32r(v);
    }
    __syncthreads();
    // Fill interior: InPad[gy+15][gx+15] = x[gy][gx], tf32-rounded.
    const float* xp = x + (long long)plane * 3136;
#pragma unroll 1
    for (int i = tid; i < 3136; i += NTH) {
        int gy = i / 56, gx = i - gy * 56;
        ip[(gy + 15) * IPSTRIDE + gx + 15] = tf32r(xp[i]);
    }
    __syncthreads();

    const int lane = tid & 31, warp = tid >> 5;
    const int g = lane >> 2, tg = lane & 3;   // groupID, thread-in-group
    const int y0 = warp * 16;

    float acc[7][4];
#pragma unroll
    for (int n = 0; n < 7; ++n)
#pragma unroll
        for (int q = 0; q < 4; ++q) acc[n][q] = 0.0f;

#pragma unroll 1
    for (int dy = 0; dy < 31; ++dy) {
        // B fragments first (broadcast loads): element = wl[8j + (tg|tg+4) - g].
        const u32* wl = wall + dy * 64 + 8;   // wl[d] = w[dy][d] (zero-padded)
        u32 b0[5], b1[5];
#pragma unroll
        for (int j = 0; j < 5; ++j) {
            b0[j] = wl[8 * j + tg - g];
            b1[j] = wl[8 * j + 4 + tg - g];
        }
        // A fragments: 11 k-tiles of InPad rows y0+dy+{g, g+8}.
        const u32* r0 = ip + (y0 + dy + g) * IPSTRIDE;
        const u32* r1 = r0 + 8 * IPSTRIDE;
        u32 a[11][4];
#pragma unroll
        for (int k = 0; k < 11; ++k) {
            a[k][0] = r0[8 * k + tg];
            a[k][1] = r1[8 * k + tg];
            a[k][2] = r0[8 * k + tg + 4];
            a[k][3] = r1[8 * k + tg + 4];
        }
        // Band-limited GEMM, j-outer: consecutive MMAs hit different acc[n].
#pragma unroll
        for (int j = 0; j < 5; ++j)
#pragma unroll
            for (int n = 0; n < 7; ++n)
                MMA(acc[n], a[n + j], b0[j], b1[j]);
    }

    // Epilogue: c0=D[g][2tg], c1=D[g][2tg+1], c2/c3 = rows g+8.
    const float bv = bias[c];
    float* op = out + (long long)plane * 3136;
    const int ylo = y0 + g, yhi = ylo + 8;   // ylo < 56 always; yhi may be >= 56
#pragma unroll
    for (int n = 0; n < 7; ++n) {
        const int xcol = 8 * n + 2 * tg;
        *reinterpret_cast<float2*>(op + ylo * 56 + xcol) =
            make_float2(acc[n][0] + bv, acc[n][1] + bv);
        if (yhi < 56)
            *reinterpret_cast<float2*>(op + yhi * 56 + xcol) =
                make_float2(acc[n][2] + bv, acc[n][3] + bv);
    }
}

extern "C" void kernel_launch(void* const* d_in, const int* in_sizes, int n_in,
                              void* d_out, int out_size)
{
    const float* x    = (const float*)d_in[0];
    const float* w    = (const float*)d_in[1];
    const float* bias = (const float*)d_in[2];
    float* out = (float*)d_out;

    // 94*100*4 + 31*64*4 = 45536 B; 5 CTAs/SM = 227.7 KB
    const int smem_bytes = (IPROWS * IPSTRIDE + 31 * 64) * 4;

    cudaFuncSetAttribute(dwconv31_tf32_hmma3_kernel,
                         cudaFuncAttributeMaxDynamicSharedMemorySize, smem_bytes);
    cudaFuncSetAttribute(dwconv31_tf32_hmma3_kernel,
                         cudaFuncAttributePreferredSharedMemoryCarveout, 100);

    dim3 grid(32 * 384);
    dim3 block(NTH);
    dwconv31_tf32_hmma3_kernel<<<grid, block, smem_bytes>>>(x, w, bias, out);
}